// round 15
// baseline (speedup 1.0000x reference)
#include <cuda_runtime.h>
#include <cuda_fp16.h>
#include <cstdint>

#define B_ 4
#define N_ 512
#define F_ 64
#define R_ 128
#define PAIRS 511                 // N-1
#define P_TOT (N_ * PAIRS)        // 261632
#define NJOBS 8192                // 4 b * 4 jt * 512 i
#define NCTAS 608                 // 2 exact waves at 2 CTAs/SM on 152 SMs

// Half-projections, BUILD-PERMUTED per 16-feature group:
// f = ks*16 + kk, kk = 2t + 8h + e  ->  pos = ks*16 + t*4 + h*2 + e
// so one float4 at (row, ks*16 + 4t) = features (2t, 2t+1, 2t+8, 2t+9):
// exactly the 4 fp32 feeding one thread's A-fragment k-slice.
__device__ float4 g_Abuf4[B_ * N_ * 32];   // A = feat @ W1[:64] + b1
__device__ float4 g_Bbuf4[B_ * N_ * 32];   // Bv = feat @ W1[64:]
// W2 packed fp16x2 in chunk layout: chunk(ks, np) = 512B, lane l=(g*4+t):
//   u32[0] = col 16np+g,   k (2t,2t+1)    u32[1] = col 16np+g,   k (2t+8,2t+9)
//   u32[2] = col 16np+8+g, k (2t,2t+1)    u32[3] = col 16np+8+g, k (2t+8,2t+9)
__device__ uint4 g_W2c[2048];

__device__ __forceinline__ void mma_f16(float* d, uint32_t a0, uint32_t a1,
                                        uint32_t a2, uint32_t a3,
                                        uint32_t b0, uint32_t b1) {
    asm volatile(
        "mma.sync.aligned.m16n8k16.row.col.f32.f16.f16.f32 "
        "{%0,%1,%2,%3}, {%4,%5,%6,%7}, {%8,%9}, {%0,%1,%2,%3};"
        : "+f"(d[0]), "+f"(d[1]), "+f"(d[2]), "+f"(d[3])
        : "r"(a0), "r"(a1), "r"(a2), "r"(a3), "r"(b0), "r"(b1));
}

// ---------------------------------------------------------------------------
// Prep: blocks [0,2048) = half-projections; blocks [2048,2056) = W2 pack.
// ---------------------------------------------------------------------------
__global__ __launch_bounds__(128) void prep_kernel(
    const float* __restrict__ feat, const float* __restrict__ W1,
    const float* __restrict__ b1, const float* __restrict__ W2) {
    const int blk = blockIdx.x;
    if (blk < B_ * N_) {
        __shared__ float sf[F_];
        const int r = threadIdx.x;
        if (r < F_) sf[r] = feat[blk * F_ + r];
        __syncthreads();
        float a = b1[r];
        float bb = 0.f;
#pragma unroll 8
        for (int f = 0; f < F_; ++f) {
            float fv = sf[f];
            a  += fv * W1[f * R_ + r];
            bb += fv * W1[(F_ + f) * R_ + r];
        }
        int pos = (r & ~15) | (((r >> 1) & 3) << 2) | (((r >> 3) & 1) << 1) | (r & 1);
        ((float*)g_Abuf4)[blk * R_ + pos] = a;
        ((float*)g_Bbuf4)[blk * R_ + pos] = bb;
    } else {
        const int w = (blk - B_ * N_) * 128 + threadIdx.x;   // 0..1023
#pragma unroll
        for (int it = 0; it < 8; ++it) {
            int uidx = w + it * 1024;           // 0..8191
            int idx = uidx & 3;
            int lane = (uidx >> 2) & 31;
            int np = (uidx >> 7) & 7;
            int ks = uidx >> 10;
            int g = lane >> 2, t = lane & 3;
            int k0 = ks * 16 + 2 * t + (idx & 1) * 8;
            int n = np * 16 + ((idx >> 1) & 1) * 8 + g;
            __half2 h = __floats2half2_rn(W2[k0 * R_ + n], W2[(k0 + 1) * R_ + n]);
            ((uint32_t*)g_W2c)[uidx] = *(uint32_t*)&h;
        }
    }
}

// ---------------------------------------------------------------------------
// Main: fp16 HMMA fused pair-MLP, persistent 2-wave grid, double-buffered h1.
// 256 threads = 8 warps: mw = w&1 (64-row half), nw = w>>1 (32-col quarter).
// Job = b*2048 + jt*512 + i (i fastest: Bv region L2-hot per CTA slice).
// SMEM: h1 buf0 32K | h1 buf1 32K | W2 32K | red 2K | b2 512 | w3 512
// ---------------------------------------------------------------------------
#define OFF_H1 0
#define OFF_W2 65536
#define OFF_RED 98304
#define OFF_B2 100352
#define OFF_W3 100864
#define SMEM_BYTES 101376

extern __shared__ char smem_raw[];

__global__ __launch_bounds__(256, 2)
void relnet_mma(const float* __restrict__ b2, const float* __restrict__ W3,
                const float* __restrict__ b3, float* __restrict__ out) {
    const int tid = threadIdx.x;
    const int warp = tid >> 5;
    const int lane = tid & 31;
    const int g = lane >> 2;
    const int t = lane & 3;
    const int mw = warp & 1;
    const int nw = warp >> 1;

    char* base = smem_raw;
    float* sRed = (float*)(base + OFF_RED);
    float* sB2 = (float*)(base + OFF_B2);
    float* sW3 = (float*)(base + OFF_W3);

    // ---- stage W2 chunks (already packed in gmem) ----
    {
        uint4* dst = (uint4*)(base + OFF_W2);
#pragma unroll
        for (int it = 0; it < 8; ++it) dst[tid + it * 256] = g_W2c[tid + it * 256];
    }
    if (tid < 128) { sB2[tid] = b2[tid]; sW3[tid] = W3[tid]; }
    const float b3v = b3[0];

    // build constants: warp w builds rows 16w+g and 16w+g+8 of the 128-row tile
    const int r1 = 16 * warp + g;
    const int r2 = r1 + 8;
    char* h1w = base + OFF_H1 + (warp * 8) * 512 + lane * 16;

    // mainloop base pointers (chunked, conflict-free LDS.128)
    const char* pAb = base + OFF_H1 + mw * 16384 + lane * 16;   // + buf*32768
    const char* pB = base + OFF_W2 + (nw * 2) * 512 + lane * 16;

    // balanced contiguous job slice for this CTA
    const int cta = blockIdx.x;
    const int lo = (int)(((long long)cta * NJOBS) / NCTAS);
    const int hi = (int)(((long long)(cta + 1) * NJOBS) / NCTAS);

    // ---- build job `job` into h1 buffer `buf` ----
    auto build = [&](int job, int buf) {
        int i = job & 511;
        int qb = ((job >> 9) & 3) * 128;
        int bb = job >> 11;
        int q1 = qb + r1, q2 = qb + r2;
        int jl1 = r1 + ((q1 >= i && q1 < PAIRS) ? 1 : 0);
        int jl2 = r2 + ((q2 >= i && q2 < PAIRS) ? 1 : 0);
        const float4* Ar = g_Abuf4 + (size_t)(bb * N_ + i) * 32 + t;
        const float4* B1 = g_Bbuf4 + (size_t)(bb * N_ + qb + jl1) * 32 + t;
        const float4* B2r = g_Bbuf4 + (size_t)(bb * N_ + qb + jl2) * 32 + t;
        char* dst = h1w + buf * 32768;
#pragma unroll
        for (int ks = 0; ks < 8; ++ks) {
            float4 av = Ar[ks * 4];
            float4 v1 = B1[ks * 4];
            float4 v2 = B2r[ks * 4];
            __half2 p0 = __floats2half2_rn(fmaxf(av.x + v1.x, 0.f),
                                           fmaxf(av.y + v1.y, 0.f));
            __half2 p1 = __floats2half2_rn(fmaxf(av.z + v1.z, 0.f),
                                           fmaxf(av.w + v1.w, 0.f));
            __half2 p2 = __floats2half2_rn(fmaxf(av.x + v2.x, 0.f),
                                           fmaxf(av.y + v2.y, 0.f));
            __half2 p3 = __floats2half2_rn(fmaxf(av.z + v2.z, 0.f),
                                           fmaxf(av.w + v2.w, 0.f));
            uint4 val;
            val.x = *(uint32_t*)&p0;   // row1, k(2t,2t+1)   = a0
            val.y = *(uint32_t*)&p1;   // row1, k(2t+8,2t+9) = a2
            val.z = *(uint32_t*)&p2;   // row2, k(2t,2t+1)   = a1
            val.w = *(uint32_t*)&p3;   // row2, k(2t+8,2t+9) = a3
            *(uint4*)(dst + ks * 512) = val;
        }
    };

    build(lo, 0);
    __syncthreads();   // W2/b2/w3 + first h1 visible

    for (int idx = lo; idx < hi; ++idx) {
        const int p = (idx - lo) & 1;
        const int job = idx;
        const int i = job & 511;
        const int qbase = ((job >> 9) & 3) * 128;
        const int b = job >> 11;

        // ---- build next job into the other buffer (overlaps mainloop) ----
        if (idx + 1 < hi) build(idx + 1, p ^ 1);

        // ---- HMMA mainloop: 64q x 32n per warp, K=128, LDS.128 frags ----
        const char* pA = pAb + p * 32768;
        float d[4][2][2][4];
#pragma unroll
        for (int mt = 0; mt < 4; ++mt)
#pragma unroll
            for (int nb = 0; nb < 2; ++nb)
#pragma unroll
                for (int nl = 0; nl < 2; ++nl)
#pragma unroll
                    for (int e = 0; e < 4; ++e) d[mt][nb][nl][e] = 0.f;

#pragma unroll
        for (int ks = 0; ks < 8; ++ks) {
            uint4 a[4];
#pragma unroll
            for (int mt = 0; mt < 4; ++mt)
                a[mt] = *(const uint4*)(pA + mt * 4096 + ks * 512);
            uint4 bb2[2];
#pragma unroll
            for (int nb = 0; nb < 2; ++nb)
                bb2[nb] = *(const uint4*)(pB + ks * 4096 + nb * 512);
#pragma unroll
            for (int mt = 0; mt < 4; ++mt)
#pragma unroll
                for (int nb = 0; nb < 2; ++nb) {
                    mma_f16(d[mt][nb][0], a[mt].x, a[mt].z, a[mt].y, a[mt].w,
                            bb2[nb].x, bb2[nb].y);
                    mma_f16(d[mt][nb][1], a[mt].x, a[mt].z, a[mt].y, a[mt].w,
                            bb2[nb].z, bb2[nb].w);
                }
        }

        // ---- epilogue: relu(+b2) dot W3, quad shuffle, 4-warp reduce ----
        float p0[4], p1[4];
        float2 bw[2][2], ww[2][2];
#pragma unroll
        for (int nb = 0; nb < 2; ++nb)
#pragma unroll
            for (int nl = 0; nl < 2; ++nl) {
                int n = nw * 32 + nb * 16 + nl * 8 + 2 * t;
                bw[nb][nl] = *(const float2*)(sB2 + n);
                ww[nb][nl] = *(const float2*)(sW3 + n);
            }
#pragma unroll
        for (int mt = 0; mt < 4; ++mt) {
            float s0 = 0.f, s1 = 0.f;
#pragma unroll
            for (int nb = 0; nb < 2; ++nb)
#pragma unroll
                for (int nl = 0; nl < 2; ++nl) {
                    const float* dd = d[mt][nb][nl];
                    s0 += fmaxf(dd[0] + bw[nb][nl].x, 0.f) * ww[nb][nl].x;
                    s0 += fmaxf(dd[1] + bw[nb][nl].y, 0.f) * ww[nb][nl].y;
                    s1 += fmaxf(dd[2] + bw[nb][nl].x, 0.f) * ww[nb][nl].x;
                    s1 += fmaxf(dd[3] + bw[nb][nl].y, 0.f) * ww[nb][nl].y;
                }
            p0[mt] = s0;
            p1[mt] = s1;
        }
#pragma unroll
        for (int v = 0; v < 4; ++v) {
            p0[v] += __shfl_xor_sync(0xffffffffu, p0[v], 1);
            p0[v] += __shfl_xor_sync(0xffffffffu, p0[v], 2);
            p1[v] += __shfl_xor_sync(0xffffffffu, p1[v], 1);
            p1[v] += __shfl_xor_sync(0xffffffffu, p1[v], 2);
        }
        {
            float v0 = (t == 0) ? p0[0] : (t == 1) ? p0[1] : (t == 2) ? p0[2] : p0[3];
            float v1 = (t == 0) ? p1[0] : (t == 1) ? p1[1] : (t == 2) ? p1[2] : p1[3];
            int r0 = mw * 64 + t * 16 + g;
            sRed[r0 * 4 + nw] = v0;
            sRed[(r0 + 8) * 4 + nw] = v1;
        }
        __syncthreads();

        if (tid < 128) {
            int qg = qbase + tid;
            if (qg < PAIRS) {
                float4 rr = *(const float4*)(sRed + tid * 4);
                out[(size_t)b * P_TOT + (size_t)i * PAIRS + qg] =
                    rr.x + rr.y + rr.z + rr.w + b3v;
            }
        }
        __syncthreads();
        // Races: build(idx+1) wrote buf p^1 (disjoint from mainloop's buf p);
        // mainloop(idx+1) reads buf p^1 only after both barriers above.
        // buf p is rewritten by build(idx+2) only after all its readers
        // (mainloop idx) passed these barriers. sRed(idx+1) writes are
        // separated from sRed(idx) reads by the final barrier.
    }
}

// ---------------------------------------------------------------------------
extern "C" void kernel_launch(void* const* d_in, const int* in_sizes, int n_in,
                              void* d_out, int out_size) {
    const float* feat = (const float*)d_in[0];
    const float* W1   = (const float*)d_in[1];
    const float* b1   = (const float*)d_in[2];
    const float* W2   = (const float*)d_in[3];
    const float* b2   = (const float*)d_in[4];
    const float* W3   = (const float*)d_in[5];
    const float* b3   = (const float*)d_in[6];
    float* out = (float*)d_out;

    prep_kernel<<<B_ * N_ + 8, 128>>>(feat, W1, b1, W2);

    cudaFuncSetAttribute(relnet_mma, cudaFuncAttributeMaxDynamicSharedMemorySize,
                         SMEM_BYTES);
    relnet_mma<<<NCTAS, 256, SMEM_BYTES>>>(b2, W3, b3, out);
}

// round 16
// speedup vs baseline: 1.1059x; 1.1059x over previous
#include <cuda_runtime.h>
#include <cuda_fp16.h>
#include <cstdint>

#define B_ 4
#define N_ 512
#define F_ 64
#define R_ 128
#define PAIRS 511                 // N-1
#define P_TOT (N_ * PAIRS)        // 261632
#define NJOBS 8192                // 4 b * 4 jt * 512 i
#define NCTAS 608                 // 2 exact waves at 2 CTAs/SM on 152 SMs

// Half-projections, BUILD-PERMUTED per 16-feature group:
// f = ks*16 + kk, kk = 2t + 8h + e  ->  pos = ks*16 + t*4 + h*2 + e
// so one float4 at (row, ks*16 + 4t) = features (2t, 2t+1, 2t+8, 2t+9):
// exactly the 4 fp32 feeding one thread's A-fragment k-slice.
__device__ float4 g_Abuf4[B_ * N_ * 32];   // A = feat @ W1[:64] + b1
__device__ float4 g_Bbuf4[B_ * N_ * 32];   // Bv = feat @ W1[64:]
// W2 packed fp16x2 in chunk layout: chunk(ks, np) = 512B, lane l=(g*4+t):
//   u32[0] = col 16np+g,   k (2t,2t+1)    u32[1] = col 16np+g,   k (2t+8,2t+9)
//   u32[2] = col 16np+8+g, k (2t,2t+1)    u32[3] = col 16np+8+g, k (2t+8,2t+9)
__device__ uint4 g_W2c[2048];

__device__ __forceinline__ void mma_f16(float* d, uint32_t a0, uint32_t a1,
                                        uint32_t a2, uint32_t a3,
                                        uint32_t b0, uint32_t b1) {
    asm volatile(
        "mma.sync.aligned.m16n8k16.row.col.f32.f16.f16.f32 "
        "{%0,%1,%2,%3}, {%4,%5,%6,%7}, {%8,%9}, {%0,%1,%2,%3};"
        : "+f"(d[0]), "+f"(d[1]), "+f"(d[2]), "+f"(d[3])
        : "r"(a0), "r"(a1), "r"(a2), "r"(a3), "r"(b0), "r"(b1));
}

// ---------------------------------------------------------------------------
// Prep: blocks [0,2048) = half-projections; blocks [2048,2056) = W2 pack.
// ---------------------------------------------------------------------------
__global__ __launch_bounds__(128) void prep_kernel(
    const float* __restrict__ feat, const float* __restrict__ W1,
    const float* __restrict__ b1, const float* __restrict__ W2) {
    const int blk = blockIdx.x;
    if (blk < B_ * N_) {
        __shared__ float sf[F_];
        const int r = threadIdx.x;
        if (r < F_) sf[r] = feat[blk * F_ + r];
        __syncthreads();
        float a = b1[r];
        float bb = 0.f;
#pragma unroll 8
        for (int f = 0; f < F_; ++f) {
            float fv = sf[f];
            a  += fv * W1[f * R_ + r];
            bb += fv * W1[(F_ + f) * R_ + r];
        }
        int pos = (r & ~15) | (((r >> 1) & 3) << 2) | (((r >> 3) & 1) << 1) | (r & 1);
        ((float*)g_Abuf4)[blk * R_ + pos] = a;
        ((float*)g_Bbuf4)[blk * R_ + pos] = bb;
    } else {
        const int w = (blk - B_ * N_) * 128 + threadIdx.x;   // 0..1023
#pragma unroll
        for (int it = 0; it < 8; ++it) {
            int uidx = w + it * 1024;           // 0..8191
            int idx = uidx & 3;
            int lane = (uidx >> 2) & 31;
            int np = (uidx >> 7) & 7;
            int ks = uidx >> 10;
            int g = lane >> 2, t = lane & 3;
            int k0 = ks * 16 + 2 * t + (idx & 1) * 8;
            int n = np * 16 + ((idx >> 1) & 1) * 8 + g;
            __half2 h = __floats2half2_rn(W2[k0 * R_ + n], W2[(k0 + 1) * R_ + n]);
            ((uint32_t*)g_W2c)[uidx] = *(uint32_t*)&h;
        }
    }
}

// ---------------------------------------------------------------------------
// Main: fp16 HMMA fused pair-MLP, 128x128 tile per job, 2 CTAs/SM,
// persistent 2-exact-wave grid (R14 phase structure, tail removed).
// 256 threads = 8 warps: mw = w&1 (64-row half), nw = w>>1 (32-col quarter).
// Job = (b*4 + jt)*512 + i (i fastest: CTA's Bv slab stays L2-hot).
// SMEM: h1 32K | W2 32K | red 2K | b2 512 | w3 512 = 68608 B
// ---------------------------------------------------------------------------
#define OFF_H1 0
#define OFF_W2 32768
#define OFF_RED 65536
#define OFF_B2 67584
#define OFF_W3 68096
#define SMEM_BYTES 68608

extern __shared__ char smem_raw[];

__global__ __launch_bounds__(256, 2)
void relnet_mma(const float* __restrict__ b2, const float* __restrict__ W3,
                const float* __restrict__ b3, float* __restrict__ out) {
    const int tid = threadIdx.x;
    const int warp = tid >> 5;
    const int lane = tid & 31;
    const int g = lane >> 2;
    const int t = lane & 3;
    const int mw = warp & 1;
    const int nw = warp >> 1;

    char* base = smem_raw;
    float* sRed = (float*)(base + OFF_RED);
    float* sB2 = (float*)(base + OFF_B2);
    float* sW3 = (float*)(base + OFF_W3);

    // ---- stage W2 chunks (already packed in gmem) ----
    {
        uint4* dst = (uint4*)(base + OFF_W2);
#pragma unroll
        for (int it = 0; it < 8; ++it) dst[tid + it * 256] = g_W2c[tid + it * 256];
    }
    if (tid < 128) { sB2[tid] = b2[tid]; sW3[tid] = W3[tid]; }
    const float b3v = b3[0];

    // build constants: warp w builds rows 16w+g and 16w+g+8 of the 128-row tile
    const int r1 = 16 * warp + g;
    const int r2 = r1 + 8;
    char* h1w = base + OFF_H1 + (warp * 8) * 512 + lane * 16;

    // mainloop base pointers (chunked, conflict-free LDS.128)
    const char* pA = base + OFF_H1 + mw * 16384 + lane * 16;    // +mt*4096 +ks*512
    const char* pB = base + OFF_W2 + (nw * 2) * 512 + lane * 16; // +ks*4096 +nb*512

    // balanced contiguous job slice for this CTA
    const int cta = blockIdx.x;
    const int lo = (int)(((long long)cta * NJOBS) / NCTAS);
    const int hi = (int)(((long long)(cta + 1) * NJOBS) / NCTAS);

    for (int job = lo; job < hi; ++job) {
        const int i = job & 511;
        const int qbase = ((job >> 9) & 3) * 128;
        const int b = job >> 11;

        // ---- build h1 chunks: relu(A_i + Bv_j) -> fp16 fragments ----
        {
            int q1 = qbase + r1, q2 = qbase + r2;
            int jl1 = r1 + ((q1 >= i && q1 < PAIRS) ? 1 : 0);
            int jl2 = r2 + ((q2 >= i && q2 < PAIRS) ? 1 : 0);
            const float4* Ar = g_Abuf4 + (size_t)(b * N_ + i) * 32 + t;
            const float4* B1 = g_Bbuf4 + (size_t)(b * N_ + qbase + jl1) * 32 + t;
            const float4* B2r = g_Bbuf4 + (size_t)(b * N_ + qbase + jl2) * 32 + t;
#pragma unroll
            for (int ks = 0; ks < 8; ++ks) {
                float4 av = Ar[ks * 4];
                float4 v1 = B1[ks * 4];
                float4 v2 = B2r[ks * 4];
                __half2 p0 = __floats2half2_rn(fmaxf(av.x + v1.x, 0.f),
                                               fmaxf(av.y + v1.y, 0.f));
                __half2 p1 = __floats2half2_rn(fmaxf(av.z + v1.z, 0.f),
                                               fmaxf(av.w + v1.w, 0.f));
                __half2 p2 = __floats2half2_rn(fmaxf(av.x + v2.x, 0.f),
                                               fmaxf(av.y + v2.y, 0.f));
                __half2 p3 = __floats2half2_rn(fmaxf(av.z + v2.z, 0.f),
                                               fmaxf(av.w + v2.w, 0.f));
                uint4 val;
                val.x = *(uint32_t*)&p0;   // row1, k(2t,2t+1)   = a0
                val.y = *(uint32_t*)&p1;   // row1, k(2t+8,2t+9) = a2
                val.z = *(uint32_t*)&p2;   // row2, k(2t,2t+1)   = a1
                val.w = *(uint32_t*)&p3;   // row2, k(2t+8,2t+9) = a3
                *(uint4*)(h1w + ks * 512) = val;
            }
        }
        __syncthreads();   // h1 (and, on first job, W2/b2/w3) visible to all

        // ---- HMMA mainloop: 64q x 32n per warp, K=128, LDS.128 frags ----
        float d[4][2][2][4];
#pragma unroll
        for (int mt = 0; mt < 4; ++mt)
#pragma unroll
            for (int nb = 0; nb < 2; ++nb)
#pragma unroll
                for (int nl = 0; nl < 2; ++nl)
#pragma unroll
                    for (int e = 0; e < 4; ++e) d[mt][nb][nl][e] = 0.f;

#pragma unroll
        for (int ks = 0; ks < 8; ++ks) {
            uint4 a[4];
#pragma unroll
            for (int mt = 0; mt < 4; ++mt)
                a[mt] = *(const uint4*)(pA + mt * 4096 + ks * 512);
            uint4 bb[2];
#pragma unroll
            for (int nb = 0; nb < 2; ++nb)
                bb[nb] = *(const uint4*)(pB + ks * 4096 + nb * 512);
#pragma unroll
            for (int mt = 0; mt < 4; ++mt)
#pragma unroll
                for (int nb = 0; nb < 2; ++nb) {
                    mma_f16(d[mt][nb][0], a[mt].x, a[mt].z, a[mt].y, a[mt].w,
                            bb[nb].x, bb[nb].y);
                    mma_f16(d[mt][nb][1], a[mt].x, a[mt].z, a[mt].y, a[mt].w,
                            bb[nb].z, bb[nb].w);
                }
        }

        // ---- epilogue: relu(+b2) dot W3, quad shuffle, 4-warp reduce ----
        float p0[4], p1[4];
        float2 bw[2][2], ww[2][2];
#pragma unroll
        for (int nb = 0; nb < 2; ++nb)
#pragma unroll
            for (int nl = 0; nl < 2; ++nl) {
                int n = nw * 32 + nb * 16 + nl * 8 + 2 * t;
                bw[nb][nl] = *(const float2*)(sB2 + n);
                ww[nb][nl] = *(const float2*)(sW3 + n);
            }
#pragma unroll
        for (int mt = 0; mt < 4; ++mt) {
            float s0 = 0.f, s1 = 0.f;
#pragma unroll
            for (int nb = 0; nb < 2; ++nb)
#pragma unroll
                for (int nl = 0; nl < 2; ++nl) {
                    const float* dd = d[mt][nb][nl];
                    s0 += fmaxf(dd[0] + bw[nb][nl].x, 0.f) * ww[nb][nl].x;
                    s0 += fmaxf(dd[1] + bw[nb][nl].y, 0.f) * ww[nb][nl].y;
                    s1 += fmaxf(dd[2] + bw[nb][nl].x, 0.f) * ww[nb][nl].x;
                    s1 += fmaxf(dd[3] + bw[nb][nl].y, 0.f) * ww[nb][nl].y;
                }
            p0[mt] = s0;
            p1[mt] = s1;
        }
#pragma unroll
        for (int v = 0; v < 4; ++v) {
            p0[v] += __shfl_xor_sync(0xffffffffu, p0[v], 1);
            p0[v] += __shfl_xor_sync(0xffffffffu, p0[v], 2);
            p1[v] += __shfl_xor_sync(0xffffffffu, p1[v], 1);
            p1[v] += __shfl_xor_sync(0xffffffffu, p1[v], 2);
        }
        {
            float v0 = (t == 0) ? p0[0] : (t == 1) ? p0[1] : (t == 2) ? p0[2] : p0[3];
            float v1 = (t == 0) ? p1[0] : (t == 1) ? p1[1] : (t == 2) ? p1[2] : p1[3];
            int r0 = mw * 64 + t * 16 + g;
            sRed[r0 * 4 + nw] = v0;
            sRed[(r0 + 8) * 4 + nw] = v1;
        }
        __syncthreads();

        if (tid < 128) {
            int qg = qbase + tid;
            if (qg < PAIRS) {
                float4 rr = *(const float4*)(sRed + tid * 4);
                out[(size_t)b * P_TOT + (size_t)i * PAIRS + qg] =
                    rr.x + rr.y + rr.z + rr.w + b3v;
            }
        }
        // next job's build (h1) is separated from this job's h1 readers by
        // the barrier above; sRed rewrite is behind the next build barrier.
    }
}

// ---------------------------------------------------------------------------
extern "C" void kernel_launch(void* const* d_in, const int* in_sizes, int n_in,
                              void* d_out, int out_size) {
    const float* feat = (const float*)d_in[0];
    const float* W1   = (const float*)d_in[1];
    const float* b1   = (const float*)d_in[2];
    const float* W2   = (const float*)d_in[3];
    const float* b2   = (const float*)d_in[4];
    const float* W3   = (const float*)d_in[5];
    const float* b3   = (const float*)d_in[6];
    float* out = (float*)d_out;

    prep_kernel<<<B_ * N_ + 8, 128>>>(feat, W1, b1, W2);

    cudaFuncSetAttribute(relnet_mma, cudaFuncAttributeMaxDynamicSharedMemorySize,
                         SMEM_BYTES);
    relnet_mma<<<NCTAS, 256, SMEM_BYTES>>>(b2, W3, b3, out);
}

// round 17
// speedup vs baseline: 1.1694x; 1.0574x over previous
#include <cuda_runtime.h>
#include <cuda_fp16.h>
#include <cstdint>

#define B_ 4
#define N_ 512
#define F_ 64
#define R_ 128
#define PAIRS 511                 // N-1
#define P_TOT (N_ * PAIRS)        // 261632
#define NJOBS 8192                // 4 b * 4 jt * 512 i
#define NCTAS 608                 // 2 exact waves at 2 CTAs/SM on 152 SMs

// Half-projections, BUILD-PERMUTED per 16-feature group:
// f = ks*16 + kk, kk = 2t + 8h + e  ->  pos = ks*16 + t*4 + h*2 + e
// so one float4 at (row, ks*16 + 4t) = features (2t, 2t+1, 2t+8, 2t+9):
// exactly the 4 fp32 feeding one thread's A-fragment k-slice.
__device__ float4 g_Abuf4[B_ * N_ * 32];   // A = feat @ W1[:64] + b1
__device__ float4 g_Bbuf4[B_ * N_ * 32];   // Bv = feat @ W1[64:]
// W2 packed fp16x2 in chunk layout: chunk(ks, np) = 512B, lane l=(g*4+t):
//   u32[0] = col 16np+g,   k (2t,2t+1)    u32[1] = col 16np+g,   k (2t+8,2t+9)
//   u32[2] = col 16np+8+g, k (2t,2t+1)    u32[3] = col 16np+8+g, k (2t+8,2t+9)
__device__ uint4 g_W2c[2048];

__device__ __forceinline__ void mma_f16(float* d, uint32_t a0, uint32_t a1,
                                        uint32_t a2, uint32_t a3,
                                        uint32_t b0, uint32_t b1) {
    asm volatile(
        "mma.sync.aligned.m16n8k16.row.col.f32.f16.f16.f32 "
        "{%0,%1,%2,%3}, {%4,%5,%6,%7}, {%8,%9}, {%0,%1,%2,%3};"
        : "+f"(d[0]), "+f"(d[1]), "+f"(d[2]), "+f"(d[3])
        : "r"(a0), "r"(a1), "r"(a2), "r"(a3), "r"(b0), "r"(b1));
}

// ---------------------------------------------------------------------------
// Prep: blocks [0,2048) = half-projections; blocks [2048,2056) = W2 pack.
// ---------------------------------------------------------------------------
__global__ __launch_bounds__(128) void prep_kernel(
    const float* __restrict__ feat, const float* __restrict__ W1,
    const float* __restrict__ b1, const float* __restrict__ W2) {
    const int blk = blockIdx.x;
    if (blk < B_ * N_) {
        __shared__ float sf[F_];
        const int r = threadIdx.x;
        if (r < F_) sf[r] = feat[blk * F_ + r];
        __syncthreads();
        float a = b1[r];
        float bb = 0.f;
#pragma unroll 8
        for (int f = 0; f < F_; ++f) {
            float fv = sf[f];
            a  += fv * W1[f * R_ + r];
            bb += fv * W1[(F_ + f) * R_ + r];
        }
        int pos = (r & ~15) | (((r >> 1) & 3) << 2) | (((r >> 3) & 1) << 1) | (r & 1);
        ((float*)g_Abuf4)[blk * R_ + pos] = a;
        ((float*)g_Bbuf4)[blk * R_ + pos] = bb;
    } else {
        const int w = (blk - B_ * N_) * 128 + threadIdx.x;   // 0..1023
#pragma unroll
        for (int it = 0; it < 8; ++it) {
            int uidx = w + it * 1024;           // 0..8191
            int idx = uidx & 3;
            int lane = (uidx >> 2) & 31;
            int np = (uidx >> 7) & 7;
            int ks = uidx >> 10;
            int g = lane >> 2, t = lane & 3;
            int k0 = ks * 16 + 2 * t + (idx & 1) * 8;
            int n = np * 16 + ((idx >> 1) & 1) * 8 + g;
            __half2 h = __floats2half2_rn(W2[k0 * R_ + n], W2[(k0 + 1) * R_ + n]);
            ((uint32_t*)g_W2c)[uidx] = *(uint32_t*)&h;
        }
    }
}

// ---------------------------------------------------------------------------
// Main: fp16 HMMA fused pair-MLP, 128x128 tile per job, 2 CTAs/SM,
// persistent 2-exact-wave grid, Bv slab staged in SMEM (fp16) per (b,jt).
// 256 threads = 8 warps: mw = w&1 (64-row half), nw = w>>1 (32-col quarter).
// Job = (b*4 + jt)*512 + i (i fastest: slab switches <=2x per CTA slice).
// SMEM: h1 32K | W2 32K | Bv slab 129x272B | red 2K | b2 512 | w3 512
// Bv slab row stride 272B (68 words): build LDS.64 conflicts <= 2-way.
// ---------------------------------------------------------------------------
#define OFF_H1 0
#define OFF_W2 32768
#define OFF_BV 65536
#define OFF_RED 100624
#define OFF_B2 102672
#define OFF_W3 103184
#define SMEM_BYTES 103696

extern __shared__ char smem_raw[];

__global__ __launch_bounds__(256, 2)
void relnet_mma(const float* __restrict__ b2, const float* __restrict__ W3,
                const float* __restrict__ b3, float* __restrict__ out) {
    const int tid = threadIdx.x;
    const int warp = tid >> 5;
    const int lane = tid & 31;
    const int g = lane >> 2;
    const int t = lane & 3;
    const int mw = warp & 1;
    const int nw = warp >> 1;

    char* base = smem_raw;
    float* sRed = (float*)(base + OFF_RED);
    float* sB2 = (float*)(base + OFF_B2);
    float* sW3 = (float*)(base + OFF_W3);

    // ---- stage W2 chunks (already packed in gmem) ----
    {
        uint4* dst = (uint4*)(base + OFF_W2);
#pragma unroll
        for (int it = 0; it < 8; ++it) dst[tid + it * 256] = g_W2c[tid + it * 256];
    }
    if (tid < 128) { sB2[tid] = b2[tid]; sW3[tid] = W3[tid]; }
    const float b3v = b3[0];

    // build constants: warp w builds rows 16w+g and 16w+g+8 of the 128-row tile
    const int r1 = 16 * warp + g;
    const int r2 = r1 + 8;
    char* h1w = base + OFF_H1 + (warp * 8) * 512 + lane * 16;

    // mainloop base pointers (chunked, conflict-free LDS.128)
    const char* pA = base + OFF_H1 + mw * 16384 + lane * 16;    // +mt*4096 +ks*512
    const char* pB = base + OFF_W2 + (nw * 2) * 512 + lane * 16; // +ks*4096 +nb*512

    // balanced contiguous job slice for this CTA
    const int cta = blockIdx.x;
    const int lo = (int)(((long long)cta * NJOBS) / NCTAS);
    const int hi = (int)(((long long)(cta + 1) * NJOBS) / NCTAS);
    int cur_slab = -1;

    for (int job = lo; job < hi; ++job) {
        const int i = job & 511;
        const int qbase = ((job >> 9) & 3) * 128;
        const int b = job >> 11;

        // ---- stage Bv slab (fp16, permuted) on (b,jt) change ----
        {
            int slab = job >> 9;
            if (slab != cur_slab) {
                cur_slab = slab;
                for (int idx2 = tid; idx2 < 129 * 64; idx2 += 256) {
                    int row = idx2 >> 6, u = idx2 & 63;
                    int sr = qbase + row;
                    if (sr > N_ - 1) sr = N_ - 1;   // jt=3 row128: never read
                    const float2* src =
                        (const float2*)(g_Bbuf4 + (size_t)(b * N_ + sr) * 32);
                    float2 x = src[u];
                    __half2 h = __floats2half2_rn(x.x, x.y);
                    *(uint32_t*)(base + OFF_BV + row * 272 + u * 4) =
                        *(uint32_t*)&h;
                }
                __syncthreads();   // slab visible before build reads it
            }
        }

        // ---- build h1 chunks: relu(A_i[f32] + Bv_j[f16]) -> fp16 frags ----
        {
            int q1 = qbase + r1, q2 = qbase + r2;
            int jl1 = r1 + ((q1 >= i && q1 < PAIRS) ? 1 : 0);
            int jl2 = r2 + ((q2 >= i && q2 < PAIRS) ? 1 : 0);
            const float4* Ar = g_Abuf4 + (size_t)(b * N_ + i) * 32 + t;
            const char* pR1 = base + OFF_BV + jl1 * 272 + t * 8;
            const char* pR2 = base + OFF_BV + jl2 * 272 + t * 8;
#pragma unroll
            for (int ks = 0; ks < 8; ++ks) {
                float4 av = Ar[ks * 4];
                uint2 u1 = *(const uint2*)(pR1 + ks * 32);
                uint2 u2 = *(const uint2*)(pR2 + ks * 32);
                float2 f0 = __half22float2(*(__half2*)&u1.x);
                float2 f1 = __half22float2(*(__half2*)&u1.y);
                float2 f2 = __half22float2(*(__half2*)&u2.x);
                float2 f3 = __half22float2(*(__half2*)&u2.y);
                __half2 p0 = __floats2half2_rn(fmaxf(av.x + f0.x, 0.f),
                                               fmaxf(av.y + f0.y, 0.f));
                __half2 p1 = __floats2half2_rn(fmaxf(av.z + f1.x, 0.f),
                                               fmaxf(av.w + f1.y, 0.f));
                __half2 p2 = __floats2half2_rn(fmaxf(av.x + f2.x, 0.f),
                                               fmaxf(av.y + f2.y, 0.f));
                __half2 p3 = __floats2half2_rn(fmaxf(av.z + f3.x, 0.f),
                                               fmaxf(av.w + f3.y, 0.f));
                uint4 val;
                val.x = *(uint32_t*)&p0;   // row1, k(2t,2t+1)   = a0
                val.y = *(uint32_t*)&p1;   // row1, k(2t+8,2t+9) = a2
                val.z = *(uint32_t*)&p2;   // row2, k(2t,2t+1)   = a1
                val.w = *(uint32_t*)&p3;   // row2, k(2t+8,2t+9) = a3
                *(uint4*)(h1w + ks * 512) = val;
            }
        }
        __syncthreads();   // h1 (and, on first job, W2/b2/w3) visible to all

        // ---- HMMA mainloop: 64q x 32n per warp, K=128, LDS.128 frags ----
        float d[4][2][2][4];
#pragma unroll
        for (int mt = 0; mt < 4; ++mt)
#pragma unroll
            for (int nb = 0; nb < 2; ++nb)
#pragma unroll
                for (int nl = 0; nl < 2; ++nl)
#pragma unroll
                    for (int e = 0; e < 4; ++e) d[mt][nb][nl][e] = 0.f;

#pragma unroll
        for (int ks = 0; ks < 8; ++ks) {
            uint4 a[4];
#pragma unroll
            for (int mt = 0; mt < 4; ++mt)
                a[mt] = *(const uint4*)(pA + mt * 4096 + ks * 512);
            uint4 bb[2];
#pragma unroll
            for (int nb = 0; nb < 2; ++nb)
                bb[nb] = *(const uint4*)(pB + ks * 4096 + nb * 512);
#pragma unroll
            for (int mt = 0; mt < 4; ++mt)
#pragma unroll
                for (int nb = 0; nb < 2; ++nb) {
                    mma_f16(d[mt][nb][0], a[mt].x, a[mt].z, a[mt].y, a[mt].w,
                            bb[nb].x, bb[nb].y);
                    mma_f16(d[mt][nb][1], a[mt].x, a[mt].z, a[mt].y, a[mt].w,
                            bb[nb].z, bb[nb].w);
                }
        }

        // ---- epilogue: relu(+b2) dot W3, quad shuffle, 4-warp reduce ----
        float p0[4], p1[4];
        float2 bw[2][2], ww[2][2];
#pragma unroll
        for (int nb = 0; nb < 2; ++nb)
#pragma unroll
            for (int nl = 0; nl < 2; ++nl) {
                int n = nw * 32 + nb * 16 + nl * 8 + 2 * t;
                bw[nb][nl] = *(const float2*)(sB2 + n);
                ww[nb][nl] = *(const float2*)(sW3 + n);
            }
#pragma unroll
        for (int mt = 0; mt < 4; ++mt) {
            float s0 = 0.f, s1 = 0.f;
#pragma unroll
            for (int nb = 0; nb < 2; ++nb)
#pragma unroll
                for (int nl = 0; nl < 2; ++nl) {
                    const float* dd = d[mt][nb][nl];
                    s0 += fmaxf(dd[0] + bw[nb][nl].x, 0.f) * ww[nb][nl].x;
                    s0 += fmaxf(dd[1] + bw[nb][nl].y, 0.f) * ww[nb][nl].y;
                    s1 += fmaxf(dd[2] + bw[nb][nl].x, 0.f) * ww[nb][nl].x;
                    s1 += fmaxf(dd[3] + bw[nb][nl].y, 0.f) * ww[nb][nl].y;
                }
            p0[mt] = s0;
            p1[mt] = s1;
        }
#pragma unroll
        for (int v = 0; v < 4; ++v) {
            p0[v] += __shfl_xor_sync(0xffffffffu, p0[v], 1);
            p0[v] += __shfl_xor_sync(0xffffffffu, p0[v], 2);
            p1[v] += __shfl_xor_sync(0xffffffffu, p1[v], 1);
            p1[v] += __shfl_xor_sync(0xffffffffu, p1[v], 2);
        }
        {
            float v0 = (t == 0) ? p0[0] : (t == 1) ? p0[1] : (t == 2) ? p0[2] : p0[3];
            float v1 = (t == 0) ? p1[0] : (t == 1) ? p1[1] : (t == 2) ? p1[2] : p1[3];
            int r0 = mw * 64 + t * 16 + g;
            sRed[r0 * 4 + nw] = v0;
            sRed[(r0 + 8) * 4 + nw] = v1;
        }
        __syncthreads();

        if (tid < 128) {
            int qg = qbase + tid;
            if (qg < PAIRS) {
                float4 rr = *(const float4*)(sRed + tid * 4);
                out[(size_t)b * P_TOT + (size_t)i * PAIRS + qg] =
                    rr.x + rr.y + rr.z + rr.w + b3v;
            }
        }
        // Races: next job's build/staging writes (h1, sBv) are separated from
        // this job's readers by the barriers above (mainloop readers passed
        // the post-build barrier; sBv readers finished before post-build
        // barrier; sRed rewrite is behind the next post-build barrier).
    }
}

// ---------------------------------------------------------------------------
extern "C" void kernel_launch(void* const* d_in, const int* in_sizes, int n_in,
                              void* d_out, int out_size) {
    const float* feat = (const float*)d_in[0];
    const float* W1   = (const float*)d_in[1];
    const float* b1   = (const float*)d_in[2];
    const float* W2   = (const float*)d_in[3];
    const float* b2   = (const float*)d_in[4];
    const float* W3   = (const float*)d_in[5];
    const float* b3   = (const float*)d_in[6];
    float* out = (float*)d_out;

    prep_kernel<<<B_ * N_ + 8, 128>>>(feat, W1, b1, W2);

    cudaFuncSetAttribute(relnet_mma, cudaFuncAttributeMaxDynamicSharedMemorySize,
                         SMEM_BYTES);
    relnet_mma<<<NCTAS, 256, SMEM_BYTES>>>(b2, W3, b3, out);
}